// round 7
// baseline (speedup 1.0000x reference)
#include <cuda_runtime.h>
#include <cstdint>

// ---------------------------------------------------------------------------
// GIN: 3 layers of { rst = h + segment_sum(h[src], dst); h = MLP2(rst) }
// N=100000, E=1600000, D=128.
//   - CSR build per launch (int atomics only)
//   - Gather aggregation (warp/node, float4/lane), L2-resident
//   - MLP on legacy tensor cores: mma.sync.m16n8k8 tf32 (sm_80+ PTX, works on
//     plain sm_103 target) with 3-term hi/lo split for fp32-level accuracy:
//       A*W ~= Ahi*Whi + Alo*Whi + Ahi*Wlo
//     fp32 tiles in smem; split to tf32 in registers at fragment load.
// ---------------------------------------------------------------------------

#define DIM 128
#define MAXN 100000
#define MAXE 1600000
#define TILE_M 128
#define SCAN_CHUNK 2048
#define MAX_SCAN_BLOCKS 64

#define SW_PITCH 133   // W^T  [n][k]  (write conflict-free: 133*4 mod 32 = 5*4)
#define SA_PITCH 132   // A    [r][k]  (frag reads conflict-free)
#define MLP_SMEM_FLOATS (128 * SW_PITCH + 128 * SA_PITCH + 256)
#define MLP_SMEM_BYTES (MLP_SMEM_FLOATS * 4)

// scratch (device globals: no allocation allowed)
__device__ int   g_deg[MAXN];
__device__ int   g_rowptr[MAXN + 1];
__device__ int   g_cursor[MAXN];
__device__ int   g_col[MAXE];
__device__ int   g_bsum[MAX_SCAN_BLOCKS];
__device__ __align__(16) float g_rst[(size_t)MAXN * DIM];
__device__ __align__(16) float g_hA [(size_t)MAXN * DIM];
__device__ __align__(16) float g_hB [(size_t)MAXN * DIM];

// ------------------------- helpers ------------------------------------------

__device__ __forceinline__ uint32_t f2tf32(float x) {
    uint32_t r;
    asm("cvt.rna.tf32.f32 %0, %1;" : "=r"(r) : "f"(x));
    return r;
}
__device__ __forceinline__ void split_tf32(float x, uint32_t& hi, uint32_t& lo) {
    hi = f2tf32(x);
    float l = x - __uint_as_float(hi);
    lo = f2tf32(l);
}

#define MMA_TF32(c, a, B0, B1)                                                  \
    asm volatile(                                                               \
        "mma.sync.aligned.m16n8k8.row.col.f32.tf32.tf32.f32 "                   \
        "{%0,%1,%2,%3}, {%4,%5,%6,%7}, {%8,%9}, {%0,%1,%2,%3};"                 \
        : "+f"((c)[0]), "+f"((c)[1]), "+f"((c)[2]), "+f"((c)[3])                \
        : "r"((a)[0]), "r"((a)[1]), "r"((a)[2]), "r"((a)[3]),                   \
          "r"(B0), "r"(B1))

// -------------------------- CSR build ---------------------------------------

__global__ void k_zero_deg(int n) {
    int i = blockIdx.x * blockDim.x + threadIdx.x;
    if (i < n) g_deg[i] = 0;
}

__global__ void k_hist(const int* __restrict__ dst, int e) {
    int i = blockIdx.x * blockDim.x + threadIdx.x;
    if (i < e) atomicAdd(&g_deg[dst[i]], 1);
}

__global__ void k_scan_reduce(int n) {
    __shared__ int s[256];
    int tid = threadIdx.x;
    int base = blockIdx.x * SCAN_CHUNK + tid * 8;
    int tot = 0;
#pragma unroll
    for (int j = 0; j < 8; ++j) {
        int idx = base + j;
        tot += (idx < n) ? g_deg[idx] : 0;
    }
    s[tid] = tot;
    __syncthreads();
    for (int off = 128; off > 0; off >>= 1) {
        if (tid < off) s[tid] += s[tid + off];
        __syncthreads();
    }
    if (tid == 0) g_bsum[blockIdx.x] = s[0];
}

__global__ void k_scan_bsum(int nb, int e, int n) {
    __shared__ int s[64];
    int t = threadIdx.x;
    int v = (t < nb) ? g_bsum[t] : 0;
    s[t] = v;
    __syncthreads();
    for (int off = 1; off < 64; off <<= 1) {
        int a = (t >= off) ? s[t - off] : 0;
        __syncthreads();
        s[t] += a;
        __syncthreads();
    }
    if (t < nb) g_bsum[t] = s[t] - v;
    if (t == 0) g_rowptr[n] = e;
}

__global__ void k_scan_final(int n) {
    __shared__ int s[256];
    int tid = threadIdx.x;
    int base = blockIdx.x * SCAN_CHUNK + tid * 8;
    int v[8];
    int run = 0;
#pragma unroll
    for (int j = 0; j < 8; ++j) {
        int idx = base + j;
        int t = (idx < n) ? g_deg[idx] : 0;
        v[j] = run;
        run += t;
    }
    int tot = run;
    s[tid] = tot;
    __syncthreads();
    for (int off = 1; off < 256; off <<= 1) {
        int add = (tid >= off) ? s[tid - off] : 0;
        __syncthreads();
        s[tid] += add;
        __syncthreads();
    }
    int texcl = s[tid] - tot;
    int pref = g_bsum[blockIdx.x] + texcl;
#pragma unroll
    for (int j = 0; j < 8; ++j) {
        int idx = base + j;
        if (idx < n) {
            int r = pref + v[j];
            g_rowptr[idx] = r;
            g_cursor[idx] = r;
        }
    }
}

__global__ void k_fill(const int* __restrict__ src, const int* __restrict__ dst, int e) {
    int i = blockIdx.x * blockDim.x + threadIdx.x;
    if (i < e) {
        int d = dst[i];
        int pos = atomicAdd(&g_cursor[d], 1);
        g_col[pos] = src[i];
    }
}

// ---------------------- aggregation (gather) --------------------------------

__global__ void __launch_bounds__(256) k_agg(const float* __restrict__ hin,
                                             float* __restrict__ rst, int n) {
    int warp = (blockIdx.x * blockDim.x + threadIdx.x) >> 5;
    int lane = threadIdx.x & 31;
    if (warp >= n) return;
    const float4* __restrict__ h4 = (const float4*)hin;
    float4 a = h4[(size_t)warp * 32 + lane];  // self, (1+eps)=1
    int s = g_rowptr[warp];
    int epos = g_rowptr[warp + 1];
    for (int i = s; i < epos; ++i) {
        int sn = g_col[i];
        float4 v = __ldg(&h4[(size_t)sn * 32 + lane]);
        a.x += v.x; a.y += v.y; a.z += v.z; a.w += v.w;
    }
    ((float4*)rst)[(size_t)warp * 32 + lane] = a;
}

// ---------------------- mma.sync tf32 GEMM core ------------------------------
// Block tile 128x128, 8 warps: warp (warp_m 0..3, warp_n 0..1) owns
// 32 rows x 64 cols = 2 mtiles(16) x 8 ntiles(8). K=128, k-step 8.
// 3-term split accumulated in fp32.

__device__ __forceinline__ void gemm_tile(const float* __restrict__ sA,
                                          const float* __restrict__ sW,
                                          const float* __restrict__ bias,
                                          int warp_m, int warp_n, int lane,
                                          float acc[2][8][4]) {
    const int gid = lane >> 2;   // 0..7
    const int tq  = lane & 3;    // 0..3

#pragma unroll
    for (int mm = 0; mm < 2; ++mm)
#pragma unroll
        for (int nn = 0; nn < 8; ++nn) {
            int cb = warp_n * 64 + nn * 8 + tq * 2;
            float bx = bias[cb], by = bias[cb + 1];
            acc[mm][nn][0] = bx; acc[mm][nn][1] = by;
            acc[mm][nn][2] = bx; acc[mm][nn][3] = by;
        }

#pragma unroll 2
    for (int ks = 0; ks < 16; ++ks) {
        const int k0 = ks * 8;
        uint32_t ahi[2][4], alo[2][4];
#pragma unroll
        for (int mm = 0; mm < 2; ++mm) {
            int r0 = warp_m * 32 + mm * 16 + gid;
            float a0 = sA[r0 * SA_PITCH + k0 + tq];
            float a1 = sA[(r0 + 8) * SA_PITCH + k0 + tq];
            float a2 = sA[r0 * SA_PITCH + k0 + tq + 4];
            float a3 = sA[(r0 + 8) * SA_PITCH + k0 + tq + 4];
            split_tf32(a0, ahi[mm][0], alo[mm][0]);
            split_tf32(a1, ahi[mm][1], alo[mm][1]);
            split_tf32(a2, ahi[mm][2], alo[mm][2]);
            split_tf32(a3, ahi[mm][3], alo[mm][3]);
        }
#pragma unroll
        for (int nn = 0; nn < 8; ++nn) {
            int nr = warp_n * 64 + nn * 8 + gid;
            float b0 = sW[nr * SW_PITCH + k0 + tq];
            float b1 = sW[nr * SW_PITCH + k0 + tq + 4];
            uint32_t bh0, bl0, bh1, bl1;
            split_tf32(b0, bh0, bl0);
            split_tf32(b1, bh1, bl1);
#pragma unroll
            for (int mm = 0; mm < 2; ++mm) {
                MMA_TF32(acc[mm][nn], ahi[mm], bh0, bh1);
                MMA_TF32(acc[mm][nn], alo[mm], bh0, bh1);
                MMA_TF32(acc[mm][nn], ahi[mm], bl0, bl1);
            }
        }
    }
}

// ---------------------- fused 2-GEMM MLP -------------------------------------
// out = act( act( A @ W1 + b1 ) @ W2 + b2 ), act = relu iff RELU.

template <bool RELU>
__global__ void __launch_bounds__(256, 1)
k_mlp(const float* __restrict__ A,
      const float* __restrict__ W1g, const float* __restrict__ b1g,
      const float* __restrict__ W2g, const float* __restrict__ b2g,
      float* __restrict__ out, int n) {
    extern __shared__ float smem[];
    float* sW    = smem;                    // 128 * SW_PITCH  (W^T: [n][k])
    float* sA    = sW + 128 * SW_PITCH;     // 128 * SA_PITCH  (A / h1: [r][k])
    float* sBias = sA + 128 * SA_PITCH;     // 256

    const int tid  = threadIdx.x;
    const int lane = tid & 31;
    const int wid  = tid >> 5;
    const int warp_m = wid & 3;
    const int warp_n = wid >> 2;
    const int row0 = blockIdx.x * TILE_M;

    if (tid < 128)      sBias[tid] = b1g[tid];
    else                sBias[tid] = b2g[tid - 128];

    // A tile (fp32, coalesced)
#pragma unroll
    for (int it = 0; it < 64; ++it) {
        int idx = tid + it * 256;         // 0..16383
        int r = idx >> 7, c = idx & 127;
        int rg = row0 + r;
        sA[r * SA_PITCH + c] = (rg < n) ? A[(size_t)rg * 128 + c] : 0.f;
    }
    // W1 transpose: sW[n][k] = W1[k][n]
#pragma unroll
    for (int it = 0; it < 64; ++it) {
        int idx = tid + it * 256;
        int k = idx >> 7, nn = idx & 127;
        sW[nn * SW_PITCH + k] = W1g[idx];
    }
    __syncthreads();

    float acc[2][8][4];
    // ---- phase 1: h1 = act(A @ W1 + b1) ----
    gemm_tile(sA, sW, sBias, warp_m, warp_n, lane, acc);
    __syncthreads();   // all phase-1 reads of sA/sW complete

    // h1 -> sA (overwrite); W2 -> sW
    {
        const int gid = lane >> 2, tq = lane & 3;
#pragma unroll
        for (int mm = 0; mm < 2; ++mm)
#pragma unroll
            for (int nn = 0; nn < 8; ++nn) {
                int r0 = warp_m * 32 + mm * 16 + gid;
                int cb = warp_n * 64 + nn * 8 + tq * 2;
                float v0 = acc[mm][nn][0], v1 = acc[mm][nn][1];
                float v2 = acc[mm][nn][2], v3 = acc[mm][nn][3];
                if (RELU) {
                    v0 = fmaxf(v0, 0.f); v1 = fmaxf(v1, 0.f);
                    v2 = fmaxf(v2, 0.f); v3 = fmaxf(v3, 0.f);
                }
                *(float2*)&sA[r0 * SA_PITCH + cb]       = make_float2(v0, v1);
                *(float2*)&sA[(r0 + 8) * SA_PITCH + cb] = make_float2(v2, v3);
            }
    }
#pragma unroll
    for (int it = 0; it < 64; ++it) {
        int idx = tid + it * 256;
        int k = idx >> 7, nn = idx & 127;
        sW[nn * SW_PITCH + k] = W2g[idx];
    }
    __syncthreads();

    // ---- phase 2: out = act(h1 @ W2 + b2) ----
    gemm_tile(sA, sW, sBias + 128, warp_m, warp_n, lane, acc);

    {
        const int gid = lane >> 2, tq = lane & 3;
#pragma unroll
        for (int mm = 0; mm < 2; ++mm)
#pragma unroll
            for (int nn = 0; nn < 8; ++nn) {
                int r0 = row0 + warp_m * 32 + mm * 16 + gid;
                int cb = warp_n * 64 + nn * 8 + tq * 2;
                float v0 = acc[mm][nn][0], v1 = acc[mm][nn][1];
                float v2 = acc[mm][nn][2], v3 = acc[mm][nn][3];
                if (RELU) {
                    v0 = fmaxf(v0, 0.f); v1 = fmaxf(v1, 0.f);
                    v2 = fmaxf(v2, 0.f); v3 = fmaxf(v3, 0.f);
                }
                if (r0 < n)
                    *(float2*)&out[(size_t)r0 * 128 + cb] = make_float2(v0, v1);
                if (r0 + 8 < n)
                    *(float2*)&out[(size_t)(r0 + 8) * 128 + cb] = make_float2(v2, v3);
            }
    }
}

// ---------------------------- host ------------------------------------------

extern "C" void kernel_launch(void* const* d_in, const int* in_sizes, int n_in,
                              void* d_out, int out_size) {
    const float* feat = (const float*)d_in[0];
    const float* W1   = (const float*)d_in[1];
    const float* b1   = (const float*)d_in[2];
    const float* W2   = (const float*)d_in[3];
    const float* b2   = (const float*)d_in[4];
    const int*   src  = (const int*)d_in[5];
    const int*   dst  = (const int*)d_in[6];

    const int n = in_sizes[0] / DIM;
    const int e = in_sizes[5];

    cudaFuncSetAttribute((const void*)k_mlp<true>,
                         cudaFuncAttributeMaxDynamicSharedMemorySize, MLP_SMEM_BYTES);
    cudaFuncSetAttribute((const void*)k_mlp<false>,
                         cudaFuncAttributeMaxDynamicSharedMemorySize, MLP_SMEM_BYTES);

    float *rst, *hA, *hB;
    cudaGetSymbolAddress((void**)&rst, g_rst);
    cudaGetSymbolAddress((void**)&hA,  g_hA);
    cudaGetSymbolAddress((void**)&hB,  g_hB);

    // ---- CSR build ----
    k_zero_deg<<<(n + 255) / 256, 256>>>(n);
    k_hist<<<(e + 255) / 256, 256>>>(dst, e);
    const int nb = (n + SCAN_CHUNK - 1) / SCAN_CHUNK;
    k_scan_reduce<<<nb, 256>>>(n);
    k_scan_bsum<<<1, 64>>>(nb, e, n);
    k_scan_final<<<nb, 256>>>(n);
    k_fill<<<(e + 255) / 256, 256>>>(src, dst, e);

    const int aggBlocks = (n + 7) / 8;
    const int mlpBlocks = (n + TILE_M - 1) / TILE_M;

    // ---- layer 0 ----
    k_agg<<<aggBlocks, 256>>>(feat, rst, n);
    k_mlp<true><<<mlpBlocks, 256, MLP_SMEM_BYTES>>>(
        rst, W1 + 0 * DIM * DIM, b1 + 0 * DIM, W2 + 0 * DIM * DIM, b2 + 0 * DIM, hA, n);
    // ---- layer 1 ----
    k_agg<<<aggBlocks, 256>>>(hA, rst, n);
    k_mlp<true><<<mlpBlocks, 256, MLP_SMEM_BYTES>>>(
        rst, W1 + 1 * DIM * DIM, b1 + 1 * DIM, W2 + 1 * DIM * DIM, b2 + 1 * DIM, hB, n);
    // ---- layer 2 (no relu) ----
    k_agg<<<aggBlocks, 256>>>(hB, rst, n);
    k_mlp<false><<<mlpBlocks, 256, MLP_SMEM_BYTES>>>(
        rst, W1 + 2 * DIM * DIM, b1 + 2 * DIM, W2 + 2 * DIM * DIM, b2 + 2 * DIM,
        (float*)d_out, n);
}

// round 8
// speedup vs baseline: 1.3873x; 1.3873x over previous
#include <cuda_runtime.h>
#include <cstdint>

// ---------------------------------------------------------------------------
// GIN: 3 layers of { rst = h + segment_sum(h[src], dst); h = MLP2(rst) }
// N=100000, E=1600000, D=128.
//   - CSR build per launch (int atomics only)
//   - FUSED layer kernel: gather-aggregate directly into smem tile, then
//     2-GEMM MLP with packed fp32 FFMA2 (fma.rn.f32x2).
//     TILE_M=64, 256 threads, ~98KB smem -> 2 blocks/SM so one block's
//     L2-bound gather overlaps the other block's FFMA2-bound compute.
//   - Last layer has no relu anywhere -> collapse its two GEMMs into one
//     via precomputed W12 = W1@W2, b12 = b1@W2 + b2.
// ---------------------------------------------------------------------------

#define DIM 128
#define MAXN 100000
#define MAXE 1600000
#define TILE_M 64
#define SA_PITCH 132
#define SMEM_FLOATS (128 * 128 + TILE_M * SA_PITCH + 256)
#define SMEM_BYTES (SMEM_FLOATS * 4)
#define SCAN_CHUNK 2048
#define MAX_SCAN_BLOCKS 64

// scratch (device globals: no allocation allowed)
__device__ int   g_deg[MAXN];
__device__ int   g_rowptr[MAXN + 1];
__device__ int   g_cursor[MAXN];
__device__ int   g_col[MAXE];
__device__ int   g_bsum[MAX_SCAN_BLOCKS];
__device__ __align__(16) float g_hA [(size_t)MAXN * DIM];
__device__ __align__(16) float g_hB [(size_t)MAXN * DIM];
__device__ __align__(16) float g_W12[DIM * DIM];
__device__ __align__(16) float g_b12[DIM];

// ------------------------- f32x2 helpers ------------------------------------

__device__ __forceinline__ unsigned long long pack2(float x, float y) {
    unsigned long long r;
    asm("mov.b64 %0, {%1, %2};" : "=l"(r) : "f"(x), "f"(y));
    return r;
}
__device__ __forceinline__ void unpack2(unsigned long long v, float& x, float& y) {
    asm("mov.b64 {%0, %1}, %2;" : "=f"(x), "=f"(y) : "l"(v));
}
__device__ __forceinline__ void fma2(unsigned long long& d,
                                     unsigned long long a, unsigned long long b) {
    asm("fma.rn.f32x2 %0, %1, %2, %0;" : "+l"(d) : "l"(a), "l"(b));
}

// -------------------------- CSR build ---------------------------------------

__global__ void k_zero_deg(int n) {
    int i = blockIdx.x * blockDim.x + threadIdx.x;
    if (i < n) g_deg[i] = 0;
}

__global__ void k_hist(const int* __restrict__ dst, int e) {
    int i = blockIdx.x * blockDim.x + threadIdx.x;
    if (i < e) atomicAdd(&g_deg[dst[i]], 1);
}

__global__ void k_scan_reduce(int n) {
    __shared__ int s[256];
    int tid = threadIdx.x;
    int base = blockIdx.x * SCAN_CHUNK + tid * 8;
    int tot = 0;
#pragma unroll
    for (int j = 0; j < 8; ++j) {
        int idx = base + j;
        tot += (idx < n) ? g_deg[idx] : 0;
    }
    s[tid] = tot;
    __syncthreads();
    for (int off = 128; off > 0; off >>= 1) {
        if (tid < off) s[tid] += s[tid + off];
        __syncthreads();
    }
    if (tid == 0) g_bsum[blockIdx.x] = s[0];
}

__global__ void k_scan_bsum(int nb, int e, int n) {
    __shared__ int s[64];
    int t = threadIdx.x;
    int v = (t < nb) ? g_bsum[t] : 0;
    s[t] = v;
    __syncthreads();
    for (int off = 1; off < 64; off <<= 1) {
        int a = (t >= off) ? s[t - off] : 0;
        __syncthreads();
        s[t] += a;
        __syncthreads();
    }
    if (t < nb) g_bsum[t] = s[t] - v;
    if (t == 0) g_rowptr[n] = e;
}

__global__ void k_scan_final(int n) {
    __shared__ int s[256];
    int tid = threadIdx.x;
    int base = blockIdx.x * SCAN_CHUNK + tid * 8;
    int v[8];
    int run = 0;
#pragma unroll
    for (int j = 0; j < 8; ++j) {
        int idx = base + j;
        int t = (idx < n) ? g_deg[idx] : 0;
        v[j] = run;
        run += t;
    }
    int tot = run;
    s[tid] = tot;
    __syncthreads();
    for (int off = 1; off < 256; off <<= 1) {
        int add = (tid >= off) ? s[tid - off] : 0;
        __syncthreads();
        s[tid] += add;
        __syncthreads();
    }
    int texcl = s[tid] - tot;
    int pref = g_bsum[blockIdx.x] + texcl;
#pragma unroll
    for (int j = 0; j < 8; ++j) {
        int idx = base + j;
        if (idx < n) {
            int r = pref + v[j];
            g_rowptr[idx] = r;
            g_cursor[idx] = r;
        }
    }
}

__global__ void k_fill(const int* __restrict__ src, const int* __restrict__ dst, int e) {
    int i = blockIdx.x * blockDim.x + threadIdx.x;
    if (i < e) {
        int d = dst[i];
        int pos = atomicAdd(&g_cursor[d], 1);
        g_col[pos] = src[i];
    }
}

// -------------------- last-layer weight folding ------------------------------
// W12[k][n] = sum_j W1[k][j] * W2[j][n];  b12[n] = sum_j b1[j]*W2[j][n] + b2[n]

__global__ void k_wfuse(const float* __restrict__ W1g, const float* __restrict__ W2g) {
    __shared__ float row[128];
    int k = blockIdx.x, nn = threadIdx.x;
    row[nn] = W1g[k * 128 + nn];
    __syncthreads();
    float acc = 0.f;
#pragma unroll 8
    for (int j = 0; j < 128; ++j) acc += row[j] * W2g[j * 128 + nn];
    g_W12[k * 128 + nn] = acc;
}

__global__ void k_bfuse(const float* __restrict__ b1g, const float* __restrict__ W2g,
                        const float* __restrict__ b2g) {
    __shared__ float bb[128];
    int nn = threadIdx.x;
    bb[nn] = b1g[nn];
    __syncthreads();
    float acc = b2g[nn];
#pragma unroll 8
    for (int j = 0; j < 128; ++j) acc += bb[j] * W2g[j * 128 + nn];
    g_b12[nn] = acc;
}

// ---------------------- shared device pieces ---------------------------------

// gather prologue: 8 warps x 8 rows; lane owns one float4 of the row.
__device__ __forceinline__ void gather_tile(const float* __restrict__ hin,
                                            float* __restrict__ sA,
                                            int row0, int n, int tid) {
    const int wid = tid >> 5, lane = tid & 31;
    const float4* __restrict__ h4 = (const float4*)hin;
#pragma unroll 1
    for (int rr = 0; rr < 8; ++rr) {
        int r  = wid * 8 + rr;
        int rg = row0 + r;
        float4 a = make_float4(0.f, 0.f, 0.f, 0.f);
        if (rg < n) {
            a = h4[(size_t)rg * 32 + lane];       // self, (1+eps)=1
            int s = g_rowptr[rg], epos = g_rowptr[rg + 1];
            for (int i = s; i < epos; ++i) {
                int sn = g_col[i];
                float4 v = __ldg(&h4[(size_t)sn * 32 + lane]);
                a.x += v.x; a.y += v.y; a.z += v.z; a.w += v.w;
            }
        }
        *(float4*)&sA[r * SA_PITCH + lane * 4] = a;
    }
}

// one 64x128x128 GEMM phase with f32x2 accumulators.
// trow = tid>>5 (rows trow*8..+7), tcol = tid&31 (cols tcol*4..+3)
__device__ __forceinline__ void gemm_phase(const float* __restrict__ sA,
                                           const float* __restrict__ sW,
                                           const float* __restrict__ bias,
                                           int r0, int c0,
                                           unsigned long long acc[8][2]) {
    unsigned long long bb0 = pack2(bias[c0],     bias[c0 + 1]);
    unsigned long long bb1 = pack2(bias[c0 + 2], bias[c0 + 3]);
#pragma unroll
    for (int i = 0; i < 8; ++i) { acc[i][0] = bb0; acc[i][1] = bb1; }
#pragma unroll 1
    for (int k0 = 0; k0 < 128; k0 += 4) {
        float4 a4[8];
#pragma unroll
        for (int i = 0; i < 8; ++i)
            a4[i] = *(const float4*)&sA[(r0 + i) * SA_PITCH + k0];
#pragma unroll
        for (int kk = 0; kk < 4; ++kk) {
            ulonglong2 w = *(const ulonglong2*)&sW[(k0 + kk) * 128 + c0];
#pragma unroll
            for (int i = 0; i < 8; ++i) {
                float av = ((const float*)&a4[i])[kk];
                unsigned long long aa = pack2(av, av);
                fma2(acc[i][0], aa, w.x);
                fma2(acc[i][1], aa, w.y);
            }
        }
    }
}

// ---------------------- fused layer: agg + 2-GEMM MLP (relu) -----------------

__global__ void __launch_bounds__(256, 2)
k_gin(const float* __restrict__ hin,
      const float* __restrict__ W1g, const float* __restrict__ b1g,
      const float* __restrict__ W2g, const float* __restrict__ b2g,
      float* __restrict__ out, int n) {
    extern __shared__ float smem[];
    float* sW    = smem;                   // 128*128
    float* sA    = sW + 128 * 128;         // 64*SA_PITCH
    float* sBias = sA + TILE_M * SA_PITCH; // 256

    const int tid  = threadIdx.x;
    const int row0 = blockIdx.x * TILE_M;

    if (tid < 128)      sBias[tid] = b1g[tid];
    else                sBias[tid] = b2g[tid - 128];

    // W1 -> sW (4096 float4 by 256 threads)
    {
        const float4* w4 = (const float4*)W1g;
        float4* s4 = (float4*)sW;
#pragma unroll
        for (int it = 0; it < 16; ++it) s4[tid + it * 256] = w4[tid + it * 256];
    }
    // aggregate tile directly into sA
    gather_tile(hin, sA, row0, n, tid);
    __syncthreads();

    const int trow = tid >> 5;   // 0..7
    const int tcol = tid & 31;   // 0..31
    const int r0 = trow * 8, c0 = tcol * 4;

    unsigned long long acc[8][2];

    // ---- phase 1: h1 = relu(A @ W1 + b1) ----
    gemm_phase(sA, sW, sBias, r0, c0, acc);
    __syncthreads();   // all phase-1 reads complete

    // h1 -> sA (overwrite), W2 -> sW
#pragma unroll
    for (int i = 0; i < 8; ++i) {
#pragma unroll
        for (int p = 0; p < 2; ++p) {
            float x, y;
            unpack2(acc[i][p], x, y);
            x = fmaxf(x, 0.f); y = fmaxf(y, 0.f);
            *(unsigned long long*)&sA[(r0 + i) * SA_PITCH + c0 + 2 * p] = pack2(x, y);
        }
    }
    {
        const float4* w4 = (const float4*)W2g;
        float4* s4 = (float4*)sW;
#pragma unroll
        for (int it = 0; it < 16; ++it) s4[tid + it * 256] = w4[tid + it * 256];
    }
    __syncthreads();

    // ---- phase 2: out = relu(h1 @ W2 + b2) ----
    gemm_phase(sA, sW, sBias + 128, r0, c0, acc);

#pragma unroll
    for (int i = 0; i < 8; ++i) {
        int rg = row0 + r0 + i;
        if (rg < n) {
            float x0, y0, x1, y1;
            unpack2(acc[i][0], x0, y0);
            unpack2(acc[i][1], x1, y1);
            x0 = fmaxf(x0, 0.f); y0 = fmaxf(y0, 0.f);
            x1 = fmaxf(x1, 0.f); y1 = fmaxf(y1, 0.f);
            ((float4*)out)[(size_t)rg * 32 + tcol] = make_float4(x0, y0, x1, y1);
        }
    }
}

// ---------------- fused last layer: agg + single folded GEMM -----------------

__global__ void __launch_bounds__(256, 2)
k_gin_last(const float* __restrict__ hin, float* __restrict__ out, int n) {
    extern __shared__ float smem[];
    float* sW    = smem;
    float* sA    = sW + 128 * 128;
    float* sBias = sA + TILE_M * SA_PITCH;

    const int tid  = threadIdx.x;
    const int row0 = blockIdx.x * TILE_M;

    if (tid < 128) sBias[tid] = g_b12[tid];

    {
        const float4* w4 = (const float4*)g_W12;
        float4* s4 = (float4*)sW;
#pragma unroll
        for (int it = 0; it < 16; ++it) s4[tid + it * 256] = w4[tid + it * 256];
    }
    gather_tile(hin, sA, row0, n, tid);
    __syncthreads();

    const int trow = tid >> 5;
    const int tcol = tid & 31;
    const int r0 = trow * 8, c0 = tcol * 4;

    unsigned long long acc[8][2];
    gemm_phase(sA, sW, sBias, r0, c0, acc);

#pragma unroll
    for (int i = 0; i < 8; ++i) {
        int rg = row0 + r0 + i;
        if (rg < n) {
            float x0, y0, x1, y1;
            unpack2(acc[i][0], x0, y0);
            unpack2(acc[i][1], x1, y1);
            ((float4*)out)[(size_t)rg * 32 + tcol] = make_float4(x0, y0, x1, y1);
        }
    }
}

// ---------------------------- host ------------------------------------------

extern "C" void kernel_launch(void* const* d_in, const int* in_sizes, int n_in,
                              void* d_out, int out_size) {
    const float* feat = (const float*)d_in[0];
    const float* W1   = (const float*)d_in[1];
    const float* b1   = (const float*)d_in[2];
    const float* W2   = (const float*)d_in[3];
    const float* b2   = (const float*)d_in[4];
    const int*   src  = (const int*)d_in[5];
    const int*   dst  = (const int*)d_in[6];

    const int n = in_sizes[0] / DIM;
    const int e = in_sizes[5];

    cudaFuncSetAttribute((const void*)k_gin,
                         cudaFuncAttributeMaxDynamicSharedMemorySize, SMEM_BYTES);
    cudaFuncSetAttribute((const void*)k_gin_last,
                         cudaFuncAttributeMaxDynamicSharedMemorySize, SMEM_BYTES);

    float *hA, *hB;
    cudaGetSymbolAddress((void**)&hA, g_hA);
    cudaGetSymbolAddress((void**)&hB, g_hB);

    // ---- CSR build + last-layer weight folding ----
    k_zero_deg<<<(n + 255) / 256, 256>>>(n);
    k_hist<<<(e + 255) / 256, 256>>>(dst, e);
    const int nb = (n + SCAN_CHUNK - 1) / SCAN_CHUNK;
    k_scan_reduce<<<nb, 256>>>(n);
    k_scan_bsum<<<1, 64>>>(nb, e, n);
    k_scan_final<<<nb, 256>>>(n);
    k_fill<<<(e + 255) / 256, 256>>>(src, dst, e);
    k_wfuse<<<128, 128>>>(W1 + 2 * DIM * DIM, W2 + 2 * DIM * DIM);
    k_bfuse<<<1, 128>>>(b1 + 2 * DIM, W2 + 2 * DIM * DIM, b2 + 2 * DIM);

    const int blocks = (n + TILE_M - 1) / TILE_M;

    // ---- layer 0 ----
    k_gin<<<blocks, 256, SMEM_BYTES>>>(
        feat, W1 + 0 * DIM * DIM, b1 + 0 * DIM, W2 + 0 * DIM * DIM, b2 + 0 * DIM, hA, n);
    // ---- layer 1 ----
    k_gin<<<blocks, 256, SMEM_BYTES>>>(
        hA, W1 + 1 * DIM * DIM, b1 + 1 * DIM, W2 + 1 * DIM * DIM, b2 + 1 * DIM, hB, n);
    // ---- layer 2 (folded single GEMM, no relu) ----
    k_gin_last<<<blocks, 256, SMEM_BYTES>>>(hB, (float*)d_out, n);
}